// round 5
// baseline (speedup 1.0000x reference)
#include <cuda_runtime.h>

// Lanczos upsample (4,2,256,256) f32 -> (4,2,2048,2048) f32, 8x per axis.
//
// Algebra (validated rounds 1-2, rel_err ~1.4e-7): the reference's
// nearest-gather + 9-tap LUT-Lanczos on the upsampled grid collapses to a 2x2
// weighted gather with 8 compile-time phase weight pairs per axis; reflect
// padding == clamp to the boundary source pixel.
//
// Round 5: row-group amortization. Output rows 8g+4..8g+11 blend the SAME
// source-row pair (clamp(g), clamp(g+1)); only (Ay,By) immediates differ.
// One block = one (channel, group): 6 loads/thread total, 8 rows emitted.
// Weights are SCALAR host constexpr variables (the only form nvcc folds into
// device code without --expt-relaxed-constexpr; arrays and constexpr-fn calls
// both fail, per rounds 3-4), selected via if-constexpr on template params.

namespace lw {

constexpr double PI = 3.14159265358979323846;

constexpr double csin(double x) {
    double k = x / (2.0 * PI);
    long long n = (long long)(k >= 0.0 ? k + 0.5 : k - 0.5);
    double r = x - (double)n * (2.0 * PI);
    if (r > PI * 0.5)       r =  PI - r;
    else if (r < -PI * 0.5) r = -PI - r;
    double term = r, sum = r;
    const double r2 = r * r;
    for (int i = 1; i <= 11; ++i) {
        term *= -r2 / ((2.0 * i) * (2.0 * i + 1.0));
        sum += term;
    }
    return sum;
}

constexpr double tap(double d, int p) {
    double t  = d + (double)(p - 4);
    double tp = t * PI;
    double tq = tp * 0.25;
    return (csin(tp) / tp) * (csin(tq) / tq);
}

constexpr float wA(int f) {
    double d = 1e-8 + (double)f / 8.0;
    int r = (f + 4) & 7;
    double a = 0.0;
    for (int p = 0; p < 8 - r; ++p) a += tap(d, p);
    return (float)a;
}
constexpr float wB(int f) {
    double d = 1e-8 + (double)f / 8.0;
    int r = (f + 4) & 7;
    double b = 0.0;
    for (int p = 8 - r; p <= 8; ++p) b += tap(d, p);
    return (float)b;
}

} // namespace lw

// 16 SCALAR constexpr weights — this exact pattern folded cleanly in round 2.
constexpr float A0 = lw::wA(0), A1 = lw::wA(1), A2 = lw::wA(2), A3 = lw::wA(3);
constexpr float A4 = lw::wA(4), A5 = lw::wA(5), A6 = lw::wA(6), A7 = lw::wA(7);
constexpr float B0 = lw::wB(0), B1 = lw::wB(1), B2 = lw::wB(2), B3 = lw::wB(3);
constexpr float B4 = lw::wB(4), B5 = lw::wB(5), B6 = lw::wB(6), B7 = lw::wB(7);

template <int F> __device__ __forceinline__ constexpr float getA() {
    if constexpr (F == 0) return A0; else if constexpr (F == 1) return A1;
    else if constexpr (F == 2) return A2; else if constexpr (F == 3) return A3;
    else if constexpr (F == 4) return A4; else if constexpr (F == 5) return A5;
    else if constexpr (F == 6) return A6; else return A7;
}
template <int F> __device__ __forceinline__ constexpr float getB() {
    if constexpr (F == 0) return B0; else if constexpr (F == 1) return B1;
    else if constexpr (F == 2) return B2; else if constexpr (F == 3) return B3;
    else if constexpr (F == 4) return B4; else if constexpr (F == 5) return B5;
    else if constexpr (F == 6) return B6; else return B7;
}

// Emit output row y = 8g+4+J (phase fy = (J+4)&7) for this thread's 8 columns.
template <int J>
__device__ __forceinline__ void emit_row(
    float* __restrict__ orow0, int g,
    float s00, float s01, float s02, float s10, float s11, float s12)
{
    const int y = 8 * g + 4 + J;
    if (y < 0 || y >= 2048) return;      // taken by only 16/2056 blocks

    constexpr float Ay = getA<(J + 4) & 7>();
    constexpr float By = getB<(J + 4) & 7>();

    const float v0 = Ay * s00 + By * s10;
    const float v1 = Ay * s01 + By * s11;
    const float v2 = Ay * s02 + By * s12;

    float4 o0, o1;
    o0.x = A0 * v0 + B0 * v1;
    o0.y = A1 * v0 + B1 * v1;
    o0.z = A2 * v0 + B2 * v1;
    o0.w = A3 * v0 + B3 * v1;
    o1.x = A4 * v1 + B4 * v2;
    o1.y = A5 * v1 + B5 * v2;
    o1.z = A6 * v1 + B6 * v2;
    o1.w = A7 * v1 + B7 * v2;

    float4* op = reinterpret_cast<float4*>(orow0 + (size_t)J * 2048);
    __stcs(op,     o0);
    __stcs(op + 1, o1);
}

// Grid: 8 channels x 257 row-groups. Group g in -1..255 covers output rows
// 8g+4..8g+11 (clipped to [0,2048)), blending source rows max(g,0), min(g+1,255).
// Thread k owns output columns 8k..8k+7 from source columns k-1,k,k+1.
__global__ void __launch_bounds__(256)
lz_upsample_kernel(const float* __restrict__ img, float* __restrict__ out) {
    const int b  = blockIdx.x;
    const int bc = b / 257;
    const int g  = (b - bc * 257) - 1;   // -1 .. 255

    const int ry0 = max(g, 0);
    const int ry1 = min(g + 1, 255);

    const float* __restrict__ base = img + (size_t)bc * 65536;
    const float* __restrict__ r0   = base + ry0 * 256;
    const float* __restrict__ r1   = base + ry1 * 256;

    const int k  = threadIdx.x;
    const int km = max(k - 1, 0);
    const int kp = min(k + 1, 255);

    const float s00 = __ldg(r0 + km), s01 = __ldg(r0 + k), s02 = __ldg(r0 + kp);
    const float s10 = __ldg(r1 + km), s11 = __ldg(r1 + k), s12 = __ldg(r1 + kp);

    float* const orow0 =
        out + ((size_t)bc * 2048 + (size_t)(8 * g + 4)) * 2048 + k * 8;

    emit_row<0>(orow0, g, s00, s01, s02, s10, s11, s12);
    emit_row<1>(orow0, g, s00, s01, s02, s10, s11, s12);
    emit_row<2>(orow0, g, s00, s01, s02, s10, s11, s12);
    emit_row<3>(orow0, g, s00, s01, s02, s10, s11, s12);
    emit_row<4>(orow0, g, s00, s01, s02, s10, s11, s12);
    emit_row<5>(orow0, g, s00, s01, s02, s10, s11, s12);
    emit_row<6>(orow0, g, s00, s01, s02, s10, s11, s12);
    emit_row<7>(orow0, g, s00, s01, s02, s10, s11, s12);
}

extern "C" void kernel_launch(void* const* d_in, const int* in_sizes, int n_in,
                              void* d_out, int out_size) {
    (void)in_sizes; (void)n_in; (void)out_size;
    const float* img = (const float*)d_in[0];
    float* out = (float*)d_out;

    lz_upsample_kernel<<<8 * 257, 256>>>(img, out);
}

// round 6
// speedup vs baseline: 1.5006x; 1.5006x over previous
#include <cuda_runtime.h>
#include <cstdint>

// Lanczos upsample (4,2,256,256) f32 -> (4,2,2048,2048) f32, 8x per axis.
//
// Algebra (validated, rel_err ~1.4e-7): reference nearest-gather + 9-tap
// LUT-Lanczos collapses to a 2x2 weighted gather with 8 compile-time phase
// weight pairs per axis; reflect padding == clamp to boundary source pixel.
//
// Round 6: same block mapping as round 2 (fastest: 1 output row / 256-thread
// block), but output egress goes SMEM -> cp.async.bulk (TMA bulk store)
// instead of per-thread STG.128. Round 5 showed the L1 pipe is dominated by
// the store stream; the bulk path moves those bytes off the L1/LSU pipe.

namespace lw {

constexpr double PI = 3.14159265358979323846;

constexpr double csin(double x) {
    double k = x / (2.0 * PI);
    long long n = (long long)(k >= 0.0 ? k + 0.5 : k - 0.5);
    double r = x - (double)n * (2.0 * PI);
    if (r > PI * 0.5)       r =  PI - r;
    else if (r < -PI * 0.5) r = -PI - r;
    double term = r, sum = r;
    const double r2 = r * r;
    for (int i = 1; i <= 11; ++i) {
        term *= -r2 / ((2.0 * i) * (2.0 * i + 1.0));
        sum += term;
    }
    return sum;
}

constexpr double tap(double d, int p) {
    double t  = d + (double)(p - 4);
    double tp = t * PI;
    double tq = tp * 0.25;
    return (csin(tp) / tp) * (csin(tq) / tq);
}

constexpr float wA(int f) {
    double d = 1e-8 + (double)f / 8.0;
    int r = (f + 4) & 7;
    double a = 0.0;
    for (int p = 0; p < 8 - r; ++p) a += tap(d, p);
    return (float)a;
}
constexpr float wB(int f) {
    double d = 1e-8 + (double)f / 8.0;
    int r = (f + 4) & 7;
    double b = 0.0;
    for (int p = 8 - r; p <= 8; ++p) b += tap(d, p);
    return (float)b;
}

} // namespace lw

// Scalar host constexprs fold into device code as literals (round-2 proven).
constexpr float A0 = lw::wA(0), A1 = lw::wA(1), A2 = lw::wA(2), A3 = lw::wA(3);
constexpr float A4 = lw::wA(4), A5 = lw::wA(5), A6 = lw::wA(6), A7 = lw::wA(7);
constexpr float B0 = lw::wB(0), B1 = lw::wB(1), B2 = lw::wB(2), B3 = lw::wB(3);
constexpr float B4 = lw::wB(4), B5 = lw::wB(5), B6 = lw::wB(6), B7 = lw::wB(7);

// y weights need a runtime index (row & 7): constant bank, uniform per block.
__constant__ float c_wA[8] = {A0, A1, A2, A3, A4, A5, A6, A7};
__constant__ float c_wB[8] = {B0, B1, B2, B3, B4, B5, B6, B7};

__device__ __forceinline__ uint32_t smem_u32(const void* p) {
    uint32_t a;
    asm("{ .reg .u64 t; cvta.to.shared.u64 t, %1; cvt.u32.u64 %0, t; }"
        : "=r"(a) : "l"(p));
    return a;
}

// One block = one output row (2048 px = 8 KB). Thread k computes the aligned
// 8-pixel phase cycle x = 8k..8k+7 from source columns k-1,k,k+1 of two source
// rows, writes to SMEM, then one thread bulk-copies the whole row to GMEM.
__global__ void __launch_bounds__(256)
lz_upsample_kernel(const float* __restrict__ img, float* __restrict__ out) {
    __shared__ __align__(128) float rowbuf[2048];

    const int row = blockIdx.x;          // (b*C+c)*2048 + y
    const int bc  = row >> 11;
    const int y   = row & 2047;

    const int fy   = y & 7;
    const int ry0u = (y - 4) >> 3;       // arithmetic shift; -1 at top edge
    const int ry0  = max(ry0u, 0);
    const int ry1  = min(ry0u + 1, 255);

    const float Ay = c_wA[fy];
    const float By = c_wB[fy];

    const float* __restrict__ base = img + (size_t)bc * 65536;
    const float* __restrict__ r0   = base + ry0 * 256;
    const float* __restrict__ r1   = base + ry1 * 256;

    const int k  = threadIdx.x;
    const int km = max(k - 1, 0);
    const int kp = min(k + 1, 255);

    // Vertical pass folded in: v_i = Ay*img[ry0,ci] + By*img[ry1,ci]
    const float v0 = Ay * __ldg(r0 + km) + By * __ldg(r1 + km);
    const float v1 = Ay * __ldg(r0 + k)  + By * __ldg(r1 + k);
    const float v2 = Ay * __ldg(r0 + kp) + By * __ldg(r1 + kp);

    // Phases 0..3: sources (k-1, k); phases 4..7: sources (k, k+1).
    float4 o0, o1;
    o0.x = A0 * v0 + B0 * v1;
    o0.y = A1 * v0 + B1 * v1;
    o0.z = A2 * v0 + B2 * v1;
    o0.w = A3 * v0 + B3 * v1;
    o1.x = A4 * v1 + B4 * v2;
    o1.y = A5 * v1 + B5 * v2;
    o1.z = A6 * v1 + B6 * v2;
    o1.w = A7 * v1 + B7 * v2;

    float4* sp = reinterpret_cast<float4*>(&rowbuf[k * 8]);
    sp[0] = o0;
    sp[1] = o1;

    __syncthreads();

    if (threadIdx.x == 0) {
        // Order generic-proxy STS before the async-proxy bulk read.
        asm volatile("fence.proxy.async.shared::cta;" ::: "memory");
        const unsigned long long gdst =
            (unsigned long long)(out + (size_t)row * 2048);
        const uint32_t ssrc = smem_u32(rowbuf);
        asm volatile(
            "cp.async.bulk.global.shared::cta.bulk_group [%0], [%1], %2;"
            :: "l"(gdst), "r"(ssrc), "n"(8192) : "memory");
        asm volatile("cp.async.bulk.commit_group;" ::: "memory");
        // Wait until the bulk engine has READ smem (safe to exit / reuse).
        asm volatile("cp.async.bulk.wait_group.read 0;" ::: "memory");
    }
}

extern "C" void kernel_launch(void* const* d_in, const int* in_sizes, int n_in,
                              void* d_out, int out_size) {
    (void)in_sizes; (void)n_in; (void)out_size;
    const float* img = (const float*)d_in[0];
    float* out = (float*)d_out;

    lz_upsample_kernel<<<16384, 256>>>(img, out);
}

// round 7
// speedup vs baseline: 1.6142x; 1.0757x over previous
#include <cuda_runtime.h>
#include <cstdint>

// Lanczos upsample (4,2,256,256) f32 -> (4,2,2048,2048) f32, 8x per axis.
//
// Algebra (validated, rel_err ~1.4e-7): reference nearest-gather + 9-tap
// LUT-Lanczos collapses to a 2x2 weighted gather with 8 compile-time phase
// weight pairs per axis; reflect padding == clamp to boundary source pixel.
//
// Round 7: 4-row blocks + single 32KB bulk store. Round 6 proved bulk-store
// egress beats per-thread STG (34.8->28.6us). Remaining L1 work is loads +
// syncs + block tails: any aligned 4-row span shares one source-row pair and
// has compile-time y-phases (block-parity dependent), so one block now does
// 6 LDG/thread ONCE, computes 4 rows into 32KB smem, and issues ONE 32KB
// cp.async.bulk (4 contiguous output rows). Grid 16384 -> 4096.

namespace lw {

constexpr double PI = 3.14159265358979323846;

constexpr double csin(double x) {
    double k = x / (2.0 * PI);
    long long n = (long long)(k >= 0.0 ? k + 0.5 : k - 0.5);
    double r = x - (double)n * (2.0 * PI);
    if (r > PI * 0.5)       r =  PI - r;
    else if (r < -PI * 0.5) r = -PI - r;
    double term = r, sum = r;
    const double r2 = r * r;
    for (int i = 1; i <= 11; ++i) {
        term *= -r2 / ((2.0 * i) * (2.0 * i + 1.0));
        sum += term;
    }
    return sum;
}

constexpr double tap(double d, int p) {
    double t  = d + (double)(p - 4);
    double tp = t * PI;
    double tq = tp * 0.25;
    return (csin(tp) / tp) * (csin(tq) / tq);
}

constexpr float wA(int f) {
    double d = 1e-8 + (double)f / 8.0;
    int r = (f + 4) & 7;
    double a = 0.0;
    for (int p = 0; p < 8 - r; ++p) a += tap(d, p);
    return (float)a;
}
constexpr float wB(int f) {
    double d = 1e-8 + (double)f / 8.0;
    int r = (f + 4) & 7;
    double b = 0.0;
    for (int p = 8 - r; p <= 8; ++p) b += tap(d, p);
    return (float)b;
}

} // namespace lw

// Scalar host constexprs fold into device code as literals (proven pattern).
constexpr float A0 = lw::wA(0), A1 = lw::wA(1), A2 = lw::wA(2), A3 = lw::wA(3);
constexpr float A4 = lw::wA(4), A5 = lw::wA(5), A6 = lw::wA(6), A7 = lw::wA(7);
constexpr float B0 = lw::wB(0), B1 = lw::wB(1), B2 = lw::wB(2), B3 = lw::wB(3);
constexpr float B4 = lw::wB(4), B5 = lw::wB(5), B6 = lw::wB(6), B7 = lw::wB(7);

template <int F> __device__ __forceinline__ constexpr float getA() {
    if constexpr (F == 0) return A0; else if constexpr (F == 1) return A1;
    else if constexpr (F == 2) return A2; else if constexpr (F == 3) return A3;
    else if constexpr (F == 4) return A4; else if constexpr (F == 5) return A5;
    else if constexpr (F == 6) return A6; else return A7;
}
template <int F> __device__ __forceinline__ constexpr float getB() {
    if constexpr (F == 0) return B0; else if constexpr (F == 1) return B1;
    else if constexpr (F == 2) return B2; else if constexpr (F == 3) return B3;
    else if constexpr (F == 4) return B4; else if constexpr (F == 5) return B5;
    else if constexpr (F == 6) return B6; else return B7;
}

__device__ __forceinline__ uint32_t smem_u32(const void* p) {
    uint32_t a;
    asm("{ .reg .u64 t; cvta.to.shared.u64 t, %1; cvt.u32.u64 %0, t; }"
        : "=r"(a) : "l"(p));
    return a;
}

// Compute row j of the 4-row span (y-phase FY = 4*PAR + j, compile time) into
// smem. x-phases 0..3 use sources (k-1,k); 4..7 use (k,k+1).
template <int FY>
__device__ __forceinline__ void compute_row(
    float* __restrict__ srow, int k,
    float s00, float s01, float s02, float s10, float s11, float s12)
{
    constexpr float Ay = getA<FY>();
    constexpr float By = getB<FY>();

    const float v0 = Ay * s00 + By * s10;
    const float v1 = Ay * s01 + By * s11;
    const float v2 = Ay * s02 + By * s12;

    float4 o0, o1;
    o0.x = A0 * v0 + B0 * v1;
    o0.y = A1 * v0 + B1 * v1;
    o0.z = A2 * v0 + B2 * v1;
    o0.w = A3 * v0 + B3 * v1;
    o1.x = A4 * v1 + B4 * v2;
    o1.y = A5 * v1 + B5 * v2;
    o1.z = A6 * v1 + B6 * v2;
    o1.w = A7 * v1 + B7 * v2;

    float4* sp = reinterpret_cast<float4*>(srow + k * 8);
    sp[0] = o0;
    sp[1] = o1;
}

// Grid: 8 channels x 512 four-row spans. Block (bc, m) produces output rows
// y = 4m..4m+3 (contiguous, 32KB), all blending source rows
// ry0 = clamp((4m-4)>>3), ry1 = ry0-span+1 clamped. Thread k owns columns
// 8k..8k+7 from source columns k-1,k,k+1.
__global__ void __launch_bounds__(256)
lz_upsample_kernel(const float* __restrict__ img, float* __restrict__ out) {
    __shared__ __align__(128) float rowbuf[4][2048];   // 32 KB

    const int b  = blockIdx.x;
    const int bc = b >> 9;               // channel 0..7
    const int m  = b & 511;              // 4-row span index

    const int y0   = 4 * m;
    const int ry0u = (y0 - 4) >> 3;      // constant across the span
    const int ry0  = max(ry0u, 0);
    const int ry1  = min(ry0u + 1, 255);

    const float* __restrict__ base = img + (size_t)bc * 65536;
    const float* __restrict__ r0   = base + ry0 * 256;
    const float* __restrict__ r1   = base + ry1 * 256;

    const int k  = threadIdx.x;
    const int km = max(k - 1, 0);
    const int kp = min(k + 1, 255);

    const float s00 = __ldg(r0 + km), s01 = __ldg(r0 + k), s02 = __ldg(r0 + kp);
    const float s10 = __ldg(r1 + km), s11 = __ldg(r1 + k), s12 = __ldg(r1 + kp);

    if (m & 1) {   // y-phases 4..7
        compute_row<4>(rowbuf[0], k, s00, s01, s02, s10, s11, s12);
        compute_row<5>(rowbuf[1], k, s00, s01, s02, s10, s11, s12);
        compute_row<6>(rowbuf[2], k, s00, s01, s02, s10, s11, s12);
        compute_row<7>(rowbuf[3], k, s00, s01, s02, s10, s11, s12);
    } else {       // y-phases 0..3
        compute_row<0>(rowbuf[0], k, s00, s01, s02, s10, s11, s12);
        compute_row<1>(rowbuf[1], k, s00, s01, s02, s10, s11, s12);
        compute_row<2>(rowbuf[2], k, s00, s01, s02, s10, s11, s12);
        compute_row<3>(rowbuf[3], k, s00, s01, s02, s10, s11, s12);
    }

    __syncthreads();

    if (threadIdx.x == 0) {
        // Order generic-proxy STS before the async-proxy bulk read.
        asm volatile("fence.proxy.async.shared::cta;" ::: "memory");
        const unsigned long long gdst =
            (unsigned long long)(out + ((size_t)bc * 2048 + (size_t)y0) * 2048);
        const uint32_t ssrc = smem_u32(rowbuf);
        asm volatile(
            "cp.async.bulk.global.shared::cta.bulk_group [%0], [%1], %2;"
            :: "l"(gdst), "r"(ssrc), "n"(32768) : "memory");
        asm volatile("cp.async.bulk.commit_group;" ::: "memory");
        // Block must not exit until the bulk engine has READ smem.
        asm volatile("cp.async.bulk.wait_group.read 0;" ::: "memory");
    }
}

extern "C" void kernel_launch(void* const* d_in, const int* in_sizes, int n_in,
                              void* d_out, int out_size) {
    (void)in_sizes; (void)n_in; (void)out_size;
    const float* img = (const float*)d_in[0];
    float* out = (float*)d_out;

    lz_upsample_kernel<<<8 * 512, 256>>>(img, out);
}